// round 15
// baseline (speedup 1.0000x reference)
#include <cuda_runtime.h>
#include <cuda_fp16.h>
#include <mma.h>
#include <cstdint>

using namespace nvcuda;

// ---------------- problem constants ----------------
namespace {
constexpr int Bb = 4, Tt = 1024, Cc = 960, Hh = 15, Nn = 64;
constexpr int Mm = Bb * Tt;                    // 4096 tokens
constexpr float LN_EPS_F = 0.00064f;
constexpr float EXP_NEG_HALF = 0.6065306597126334f;

constexpr size_t MC  = (size_t)Mm * Cc;
constexpr size_t SZ_H_MC = MC * 2;
constexpr size_t SZ_F_MC = MC * 4;

constexpr size_t O_XR   = 0;
constexpr size_t O_XW   = O_XR + SZ_H_MC;
constexpr size_t O_XK   = O_XW + SZ_H_MC;
constexpr size_t O_XV   = O_XK + SZ_H_MC;
constexpr size_t O_XA   = O_XV + SZ_H_MC;
constexpr size_t O_XG   = O_XA + SZ_H_MC;
constexpr size_t O_WR16 = O_XG + SZ_H_MC;
constexpr size_t O_WK16 = O_WR16 + (size_t)Cc * Cc * 2;
constexpr size_t O_WV16 = O_WK16 + (size_t)Cc * Cc * 2;
constexpr size_t O_WO16 = O_WV16 + (size_t)Cc * Cc * 2;
constexpr size_t O_W116 = O_WO16 + (size_t)Cc * Cc * 2;
constexpr size_t O_A116 = O_W116 + (size_t)Cc * 64 * 2;
constexpr size_t O_V116 = O_A116 + (size_t)Cc * 64 * 2;
constexpr size_t O_G116 = O_V116 + (size_t)Cc * 32 * 2;
constexpr size_t O_W216 = O_G116 + (size_t)Cc * 128 * 2;
constexpr size_t O_A216 = O_W216 + (size_t)64 * Cc * 2;
constexpr size_t O_V216 = O_A216 + (size_t)64 * Cc * 2;
constexpr size_t O_G216 = O_V216 + (size_t)32 * Cc * 2;
constexpr size_t O_HW   = O_G216 + (size_t)128 * Cc * 2;
constexpr size_t O_HA   = O_HW + (size_t)Mm * 64 * 2;
constexpr size_t O_HV   = O_HA + (size_t)Mm * 64 * 2;
constexpr size_t O_HG   = O_HV + (size_t)Mm * 32 * 2;
// fp16 intermediates (fp32-sized slots)
constexpr size_t O_R    = O_HG + (size_t)Mm * 128 * 2;
constexpr size_t O_K    = O_R + SZ_F_MC;
constexpr size_t O_V    = O_K + SZ_F_MC;
constexpr size_t O_WRAW = O_V + SZ_F_MC;
constexpr size_t O_ARAW = O_WRAW + SZ_F_MC;
constexpr size_t O_VRAW = O_ARAW + SZ_F_MC;
constexpr size_t O_GG   = O_VRAW + SZ_F_MC;
// interleaved scan input: [bh][t][6][64] fp32
constexpr size_t O_SS   = O_GG + SZ_F_MC;
constexpr size_t SZ_SS  = (size_t)Bb * Hh * Tt * 6 * 64 * 4;
constexpr size_t O_COEF = O_SS + SZ_SS;
constexpr size_t O_WKV  = O_COEF + (size_t)Bb * Hh * Tt * 4;
constexpr size_t O_XO   = O_WKV + SZ_F_MC;
constexpr size_t SCRATCH_TOTAL = O_XO + SZ_H_MC;

// GEMM config: 128x128 CTA, 8 warps 2Mx4N, 64x32 warp tile (proven)
constexpr int FBM = 128, FBN = 128, FBK = 32;
constexpr int FLDA = 40, FLDB = 136;
constexpr int NSTG = 3;
constexpr int STAGE_A = FBM * FLDA;
constexpr int STAGE_B = FBK * FLDB;
constexpr int K2_SMEM = NSTG * (STAGE_A + STAGE_B) * 2;
constexpr int UPLDC = 132;
constexpr int UP_SMEM = (FBM * UPLDC * 4) > K2_SMEM ? (FBM * UPLDC * 4) : K2_SMEM;

// scan pipeline
constexpr int SCAN_D = 8;
constexpr int SCAN_STAGE_F = 336;
} // namespace

__device__ __align__(256) unsigned char g_scratch[SCRATCH_TOTAL];

// ---------------- helpers ----------------
__device__ __forceinline__ float sigmoidf_(float x) { return 1.f / (1.f + expf(-x)); }
__device__ __forceinline__ float getc(const float4& v, int j) {
    return j == 0 ? v.x : j == 1 ? v.y : j == 2 ? v.z : v.w;
}
__device__ __forceinline__ float2 h2f2(const __half* p) {
    return __half22float2(*(const __half2*)p);
}
__device__ __forceinline__ void cp_async16(void* smem_dst, const void* gsrc) {
    unsigned int d = (unsigned int)__cvta_generic_to_shared(smem_dst);
    asm volatile("cp.async.cg.shared.global [%0], [%1], 16;" :: "r"(d), "l"(gsrc));
}
__device__ __forceinline__ void cp_async16p(void* smem_dst, const void* gsrc, bool pred) {
    unsigned int d = (unsigned int)__cvta_generic_to_shared(smem_dst);
    int b = pred ? 16 : 0;
    asm volatile("cp.async.cg.shared.global [%0], [%1], 16, %2;" :: "r"(d), "l"(gsrc), "r"(b));
}
#define CP_COMMIT() asm volatile("cp.async.commit_group;")
#define CP_WAIT2()  asm volatile("cp.async.wait_group 2;")
#define CP_WAIT7()  asm volatile("cp.async.wait_group 7;")

// ---------------- fused weight convert ----------------
__global__ void k_convert_all(const float* p0, const float* p1, const float* p2,
                              const float* p3, const float* p4, const float* p5,
                              const float* p6, const float* p7, const float* p8,
                              const float* p9, const float* p10, const float* p11) {
    const int sizes[12] = {Cc * Cc, Cc * Cc, Cc * Cc, Cc * Cc,
                           Cc * 64, Cc * 64, Cc * 32, Cc * 128,
                           64 * Cc, 64 * Cc, 32 * Cc, 128 * Cc};
    const size_t doff[12] = {O_WR16, O_WK16, O_WV16, O_WO16,
                             O_W116, O_A116, O_V116, O_G116,
                             O_W216, O_A216, O_V216, O_G216};
    const float* srcs[12] = {p0, p1, p2, p3, p4, p5, p6, p7, p8, p9, p10, p11};
    int z = blockIdx.y;
    int n = sizes[z];
    int i = (blockIdx.x * 256 + threadIdx.x) * 4;
    if (i >= n) return;
    const float* s = srcs[z];
    __half* d = (__half*)(g_scratch + doff[z]);
    float4 v = *(const float4*)(s + i);
    *(__half2*)(d + i)     = __floats2half2_rn(v.x, v.y);
    *(__half2*)(d + i + 2) = __floats2half2_rn(v.z, v.w);
}

// ---------------- token shift + mix ----------------
__global__ void k_mix(const float* __restrict__ x,
                      const float* __restrict__ mr, const float* __restrict__ mw,
                      const float* __restrict__ mk, const float* __restrict__ mv,
                      const float* __restrict__ ma, const float* __restrict__ mg) {
    int i = blockIdx.x * blockDim.x + threadIdx.x;
    if (i >= Mm * (Cc / 4)) return;
    int m = i / (Cc / 4);
    int c = (i % (Cc / 4)) * 4;
    int t = m & (Tt - 1);
    float4 xc = *(const float4*)(x + (size_t)m * Cc + c);
    float4 xp = make_float4(0.f, 0.f, 0.f, 0.f);
    if (t > 0) xp = *(const float4*)(x + (size_t)(m - 1) * Cc + c);
    float4 dx = make_float4(xp.x - xc.x, xp.y - xc.y, xp.z - xc.z, xp.w - xc.w);

    const float* mixes[6] = {mr, mw, mk, mv, ma, mg};
    const size_t offs[6] = {O_XR, O_XW, O_XK, O_XV, O_XA, O_XG};
#pragma unroll
    for (int q = 0; q < 6; q++) {
        float4 mmv = *(const float4*)(mixes[q] + c);
        __half* out = (__half*)(g_scratch + offs[q]);
        __half2 h0 = __floats2half2_rn(xc.x + dx.x * mmv.x, xc.y + dx.y * mmv.y);
        __half2 h1 = __floats2half2_rn(xc.z + dx.z * mmv.z, xc.w + dx.w * mmv.w);
        *(__half2*)(out + (size_t)m * Cc + c)     = h0;
        *(__half2*)(out + (size_t)m * Cc + c + 2) = h1;
    }
}

// ---------------- GEMM compute core: 3-stage cp.async (proven) ----------
__device__ __forceinline__ void gemm_core(const __half* __restrict__ A,
                                          const __half* __restrict__ Bm,
                                          int Nd, int Kd, int bm, int bn,
                                          __half* sA, __half* sB,
                                          wmma::fragment<wmma::accumulator, 16, 16, 16, float> (&acc)[4][2]) {
    int tid = threadIdx.x;
    int warp = tid >> 5;
    int wr = warp >> 2;
    int wc = warp & 3;
    int KT = Kd / FBK;

    auto load_stage = [&](int kt, int s) {
        const __half* Ag = A + (size_t)bm * Kd + kt * FBK;
        __half* sAs = sA + s * STAGE_A;
        __half* sBs = sB + s * STAGE_B;
#pragma unroll
        for (int u = 0; u < 2; u++) {
            int id = tid + u * 256;
            int r = id >> 2;
            int c = (id & 3) * 8;
            cp_async16(sAs + r * FLDA + c, Ag + (size_t)r * Kd + c);
        }
#pragma unroll
        for (int u = 0; u < 2; u++) {
            int id = tid + u * 256;
            int r = id >> 4;
            int c = (id & 15) * 8;
            bool p = (bn + c) < Nd;
            const __half* Bg = Bm + (size_t)(kt * FBK + r) * Nd + bn + c;
            cp_async16p(sBs + r * FLDB + c, p ? Bg : (const __half*)Bm, p);
        }
    };

#pragma unroll
    for (int i = 0; i < 4; i++)
#pragma unroll
        for (int j = 0; j < 2; j++) wmma::fill_fragment(acc[i][j], 0.f);

    load_stage(0, 0);
    CP_COMMIT();
    if (KT > 1) load_stage(1, 1);
    CP_COMMIT();

    for (int kt = 0; kt < KT; kt++) {
        if (kt + 2 < KT) load_stage(kt + 2, (kt + 2) % NSTG);
        CP_COMMIT();
        CP_WAIT2();
        __syncthreads();
        const __half* sAs = sA + (kt % NSTG) * STAGE_A;
        const __half* sBs = sB + (kt % NSTG) * STAGE_B;
#pragma unroll
        for (int ks = 0; ks < 2; ks++) {
            wmma::fragment<wmma::matrix_b, 16, 16, 16, __half, wmma::row_major> fb[2];
            wmma::load_matrix_sync(fb[0], sBs + (ks * 16) * FLDB + wc * 32, FLDB);
            wmma::load_matrix_sync(fb[1], sBs + (ks * 16) * FLDB + wc * 32 + 16, FLDB);
#pragma unroll
            for (int i = 0; i < 4; i++) {
                wmma::fragment<wmma::matrix_a, 16, 16, 16, __half, wmma::row_major> fa;
                wmma::load_matrix_sync(fa, sAs + (wr * 64 + i * 16) * FLDA + ks * 16, FLDA);
                wmma::mma_sync(acc[i][0], fa, fb[0], acc[i][0]);
                wmma::mma_sync(acc[i][1], fa, fb[1], acc[i][1]);
            }
        }
        __syncthreads();
    }
}

// fp32 direct-store GEMM (final output only)
__global__ void __launch_bounds__(256, 2) k2_gemm_out(float* __restrict__ out) {
    extern __shared__ __align__(16) unsigned char dyn[];
    __half* sA = (__half*)dyn;
    __half* sB = sA + NSTG * STAGE_A;
    wmma::fragment<wmma::accumulator, 16, 16, 16, float> acc[4][2];
    int bm = blockIdx.y * FBM;
    int bn = blockIdx.x * FBN;
    gemm_core((const __half*)(g_scratch + O_XO), (const __half*)(g_scratch + O_WO16),
              Cc, Cc, bm, bn, sA, sB, acc);
    int warp = threadIdx.x >> 5;
    int wr = warp >> 2;
    int wc = warp & 3;
#pragma unroll
    for (int i = 0; i < 4; i++)
#pragma unroll
        for (int j = 0; j < 2; j++) {
            int gc = bn + wc * 32 + j * 16;
            if (gc < Cc)
                wmma::store_matrix_sync(out + (size_t)(bm + wr * 64 + i * 16) * Cc + gc,
                                        acc[i][j], Cc, wmma::mem_row_major);
        }
}

// fp16-output GEMM via smem-staged epilogue
__device__ __forceinline__ void gemm_f16_epi(const __half* A, const __half* Bm,
                                             __half* Cout, int Nd, int Kd,
                                             int bm, int bn, unsigned char* dyn) {
    __half* sA = (__half*)dyn;
    __half* sB = sA + NSTG * STAGE_A;
    float*  sC = (float*)dyn;

    wmma::fragment<wmma::accumulator, 16, 16, 16, float> acc[4][2];
    gemm_core(A, Bm, Nd, Kd, bm, bn, sA, sB, acc);

    int tid = threadIdx.x;
    int warp = tid >> 5;
    int wr = warp >> 2;
    int wc = warp & 3;
#pragma unroll
    for (int i = 0; i < 4; i++)
#pragma unroll
        for (int j = 0; j < 2; j++)
            wmma::store_matrix_sync(sC + (wr * 64 + i * 16) * UPLDC + wc * 32 + j * 16,
                                    acc[i][j], UPLDC, wmma::mem_row_major);
    __syncthreads();

    for (int idx = tid; idx < FBM * FBN / 2; idx += 256) {
        int r = idx / (FBN / 2);
        int c2 = (idx % (FBN / 2)) * 2;
        int gc = bn + c2;
        if (gc >= Nd) continue;
        float v0 = sC[r * UPLDC + c2];
        float v1 = sC[r * UPLDC + c2 + 1];
        *(__half2*)(Cout + (size_t)(bm + r) * Nd + gc) = __floats2half2_rn(v0, v1);
    }
}

// rkv with z offset so R/K and V can go on different streams
__global__ void __launch_bounds__(256, 2) k2_gemm_rkv(int z_off) {
    extern __shared__ __align__(16) unsigned char dyn[];
    int z = blockIdx.z + z_off;
    const size_t aoff[3] = {O_XR, O_XK, O_XV};
    const size_t boff[3] = {O_WR16, O_WK16, O_WV16};
    const size_t coff[3] = {O_R, O_K, O_V};
    gemm_f16_epi((const __half*)(g_scratch + aoff[z]), (const __half*)(g_scratch + boff[z]),
                 (__half*)(g_scratch + coff[z]), Cc, Cc,
                 blockIdx.y * FBM, blockIdx.x * FBN, dyn);
}

__global__ void __launch_bounds__(256, 2) k2_gemm_down() {
    extern __shared__ __align__(16) unsigned char dyn[];
    int z = blockIdx.z;
    const size_t aoff[4] = {O_HW, O_HA, O_HV, O_HG};
    const size_t boff[4] = {O_W216, O_A216, O_V216, O_G216};
    const size_t coff[4] = {O_WRAW, O_ARAW, O_VRAW, O_GG};
    const int kd[4] = {64, 64, 32, 128};
    gemm_f16_epi((const __half*)(g_scratch + aoff[z]), (const __half*)(g_scratch + boff[z]),
                 (__half*)(g_scratch + coff[z]), Cc, kd[z],
                 blockIdx.y * FBM, blockIdx.x * FBN, dyn);
}

// lora-up: fp16 + activation epilogue via smem staging
__global__ void __launch_bounds__(256, 2) k2_gemm_up() {
    extern __shared__ __align__(16) unsigned char dyn[];
    __half* sA = (__half*)dyn;
    __half* sB = sA + NSTG * STAGE_A;
    float*  sC = (float*)dyn;

    int z = blockIdx.z;
    const size_t aoff[4] = {O_XW, O_XA, O_XV, O_XG};
    const size_t boff[4] = {O_W116, O_A116, O_V116, O_G116};
    const size_t coff[4] = {O_HW, O_HA, O_HV, O_HG};
    const int ndA[4] = {64, 64, 32, 128};
    const int epA[4] = {1, 3, 3, 2};
    int Nd = ndA[z];
    int epi = epA[z];
    int bm = blockIdx.y * FBM;

    wmma::fragment<wmma::accumulator, 16, 16, 16, float> acc[4][2];
    gemm_core((const __half*)(g_scratch + aoff[z]), (const __half*)(g_scratch + boff[z]),
              Nd, Cc, bm, 0, sA, sB, acc);

    int tid = threadIdx.x;
    int warp = tid >> 5;
    int wr = warp >> 2;
    int wc = warp & 3;
#pragma unroll
    for (int i = 0; i < 4; i++)
#pragma unroll
        for (int j = 0; j < 2; j++)
            wmma::store_matrix_sync(sC + (wr * 64 + i * 16) * UPLDC + wc * 32 + j * 16,
                                    acc[i][j], UPLDC, wmma::mem_row_major);
    __syncthreads();

    __half* Cout = (__half*)(g_scratch + coff[z]);
    for (int idx = tid; idx < FBM * 128; idx += 256) {
        int r = idx >> 7;
        int c = idx & 127;
        if (c >= Nd) continue;
        float v = sC[r * UPLDC + c];
        if (epi == 1)      v = tanhf(v);
        else if (epi == 2) v = sigmoidf_(v);
        Cout[(size_t)(bm + r) * Nd + c] = __float2half(v);
    }
}

// ---------------- per-token prepare (fp16 inputs; interleaved [6][64] fp32 out) -----------
__global__ void k_prepare(const float* __restrict__ vfirst,
                          const float* __restrict__ w0, const float* __restrict__ a0,
                          const float* __restrict__ v0, const float* __restrict__ kkw,
                          const float* __restrict__ kaw, const float* __restrict__ rkw) {
    const __half* Rf   = (const __half*)(g_scratch + O_R);
    const __half* Kf   = (const __half*)(g_scratch + O_K);
    const __half* Vf   = (const __half*)(g_scratch + O_V);
    const __half* WRAW = (const __half*)(g_scratch + O_WRAW);
    const __half* ARAW = (const __half*)(g_scratch + O_ARAW);
    const __half* VRAW = (const __half*)(g_scratch + O_VRAW);
    float* SS   = (float*)(g_scratch + O_SS);
    float* COEF = (float*)(g_scratch + O_COEF);

    int gw = (blockIdx.x * blockDim.x + threadIdx.x) >> 5;
    int lane = threadIdx.x & 31;
    if (gw >= Mm * Hh) return;
    int m = gw / Hh;
    int h = gw % Hh;
    int b = m >> 10;
    int t = m & (Tt - 1);
    int n = lane * 2;
    int c = h * Nn + n;
    size_t gbase = (size_t)m * Cc + c;

    float2 k2   = h2f2(Kf + gbase);
    float2 kkwv = *(const float2*)(kkw + c);
    float kkx = k2.x * kkwv.x, kky = k2.y * kkwv.y;
    float ss = kkx * kkx + kky * kky;
#pragma unroll
    for (int o = 16; o; o >>= 1) ss += __shfl_xor_sync(0xffffffffu, ss, o);
    float inv = 1.f / fmaxf(sqrtf(ss), 1e-12f);

    float2 ar2 = h2f2(ARAW + gbase);
    float2 a0v = *(const float2*)(a0 + c);
    float ax = sigmoidf_(a0v.x + ar2.x);
    float ay = sigmoidf_(a0v.y + ar2.y);

    float2 kav = *(const float2*)(kaw + c);
    float khx = k2.x * (1.f + (ax - 1.f) * kav.x);
    float khy = k2.y * (1.f + (ay - 1.f) * kav.y);

    float2 wr2 = h2f2(WRAW + gbase);
    float2 w0v = *(const float2*)(w0 + c);
    float wx = EXP_NEG_HALF * sigmoidf_(w0v.x + wr2.x);
    float wy = EXP_NEG_HALF * sigmoidf_(w0v.y + wr2.y);

    float2 vr2 = h2f2(VRAW + gbase);
    float2 v0v = *(const float2*)(v0 + c);
    float svx = sigmoidf_(v0v.x + vr2.x);
    float svy = sigmoidf_(v0v.y + vr2.y);
    float2 vv  = h2f2(Vf + gbase);
    float2 vf2 = *(const float2*)(vfirst + gbase);
    float vhx = vv.x + (vf2.x - vv.x) * svx;
    float vhy = vv.y + (vf2.y - vv.y) * svy;

    float2 r2  = h2f2(Rf + gbase);
    float2 rkv = *(const float2*)(rkw + c);
    float cf = r2.x * khx * rkv.x + r2.y * khy * rkv.y;
#pragma unroll
    for (int o = 16; o; o >>= 1) cf += __shfl_xor_sync(0xffffffffu, cf, o);

    int bh = b * Hh + h;
    float* tok = SS + ((size_t)bh * Tt + t) * 384 + n;
    *(float2*)(tok + 0 * 64) = make_float2(wx, wy);
    *(float2*)(tok + 1 * 64) = make_float2(-kkx * inv, -kky * inv);
    *(float2*)(tok + 2 * 64) = make_float2(kkx * inv * ax, kky * inv * ay);
    *(float2*)(tok + 3 * 64) = make_float2(khx, khy);
    *(float2*)(tok + 4 * 64) = r2;
    *(float2*)(tok + 5 * 64) = make_float2(vhx, vhy);
    if (lane == 0) COEF[(size_t)bh * Tt + t] = cf;
}

// ---------------- scan: single-warp blocks, no __syncthreads (proven) ------------
__global__ void __launch_bounds__(32) k_scan() {
    __shared__ __align__(16) float sbuf[SCAN_D][SCAN_STAGE_F];

    const float* SS = (const float*)(g_scratch + O_SS);
    float* WKV = (float*)(g_scratch + O_WKV);

    int blk = blockIdx.x;
    int bh = blk >> 4;
    int q = blk & 15;
    int lane = threadIdx.x;
    int rowl = lane >> 3;
    int cg = lane & 7;
    int row = q * 4 + rowl;
    size_t base = (size_t)bh * Tt * Nn;
    size_t base_ss = (size_t)bh * Tt * 384;
    int co = cg * 8;

    auto issue_stage = [&](int t) {
        int slot = t & (SCAN_D - 1);
        const float* src = SS + base_ss + (size_t)t * 384;
#pragma unroll
        for (int c = lane; c < 80; c += 32)
            cp_async16(&sbuf[slot][c * 4], src + c * 4);
        if (lane == 0)
            cp_async16(&sbuf[slot][320], src + 5 * 64 + q * 4);
    };

#pragma unroll
    for (int s = 0; s < SCAN_D - 1; s++) {
        issue_stage(s);
        CP_COMMIT();
    }

    float st[8];
#pragma unroll
    for (int j = 0; j < 8; j++) st[j] = 0.f;

    for (int t = 0; t < Tt; t++) {
        __syncwarp();
        int tp = t + SCAN_D - 1;
        if (tp < Tt) issue_stage(tp);
        CP_COMMIT();
        CP_WAIT7();
        __syncwarp();

        const float* S = sbuf[t & (SCAN_D - 1)];
        float4 wv0 = *(const float4*)(S + 0 * 64 + co);
        float4 wv1 = *(const float4*)(S + 0 * 64 + co + 4);
        float4 av0 = *(const float4*)(S + 1 * 64 + co);
        float4 av1 = *(const float4*)(S + 1 * 64 + co + 4);
        float4 bv0 = *(const float4*)(S + 2 * 64 + co);
        float4 bv1 = *(const float4*)(S + 2 * 64 + co + 4);
        float4 kv0 = *(const float4*)(S + 3 * 64 + co);
        float4 kv1 = *(const float4*)(S + 3 * 64 + co + 4);
        float4 rv0 = *(const float4*)(S + 4 * 64 + co);
        float4 rv1 = *(const float4*)(S + 4 * 64 + co + 4);
        float cv = S[320 + rowl];

        float sa = 0.f;
#pragma unroll
        for (int j = 0; j < 8; j++)
            sa = fmaf(st[j], getc(j < 4 ? av0 : av1, j & 3), sa);
        sa += __shfl_xor_sync(0xffffffffu, sa, 1);
        sa += __shfl_xor_sync(0xffffffffu, sa, 2);
        sa += __shfl_xor_sync(0xffffffffu, sa, 4);

        float outp = 0.f;
#pragma unroll
        for (int j = 0; j < 8; j++) {
            float wj = getc(j < 4 ? wv0 : wv1, j & 3);
            float bj = getc(j < 4 ? bv0 : bv1, j & 3);
            float kj = getc(j < 4 ? kv0 : kv1, j & 3);
            float rj = getc(j < 4 ? rv0 : rv1, j & 3);
            float s = fmaf(st[j], wj, fmaf(sa, bj, cv * kj));
            st[j] = s;
            outp = fmaf(s, rj, outp);
        }
        outp += __shfl_xor_sync(0xffffffffu, outp, 1);
        outp += __shfl_xor_sync(0xffffffffu, outp, 2);
        outp += __shfl_xor_sync(0xffffffffu, outp, 4);
        if (cg == 0) WKV[base + (size_t)t * Nn + row] = outp;
    }
}

// ---------------- groupnorm + bonus + gate ----------------
__global__ void k_gn(const float* __restrict__ lng, const float* __restrict__ lnb) {
    const float* WKV  = (const float*)(g_scratch + O_WKV);
    const float* SS   = (const float*)(g_scratch + O_SS);
    const float* COEF = (const float*)(g_scratch + O_COEF);
    const __half* GG  = (const __half*)(g_scratch + O_GG);
    __half* XO = (__half*)(g_scratch + O_XO);

    int gw = (blockIdx.x * blockDim.x + threadIdx.x) >> 5;
    int lane = threadIdx.x & 31;
    if (gw >= Mm * Hh) return;
    int m = gw / Hh;
    int h = gw % Hh;
    int b = m >> 10;
    int t = m & (Tt - 1);
    int bh = b * Hh + h;
    int n = lane * 2;
    int c = h * Nn + n;
    size_t tok = (size_t)bh * Tt + t;
    size_t sbase = tok * Nn + n;

    float2 x2 = *(const float2*)(WKV + sbase);
    float s1 = x2.x + x2.y;
    float s2 = x2.x * x2.x + x2.y * x2.y;
#pragma unroll
    for (int o = 16; o; o >>= 1) {
        s1 += __shfl_xor_sync(0xffffffffu, s1, o);
        s2 += __shfl_xor_sync(0xffffffffu, s2, o);
    }
    float mu = s1 * (1.f / 64.f);
    float var = s2 * (1.f / 64.f) - mu * mu;
    float inv = rsqrtf(fmaxf(var, 0.f) + LN_EPS_F);

    float2 g2v = *(const float2*)(lng + c);
    float2 b2v = *(const float2*)(lnb + c);
    float xn0 = (x2.x - mu) * inv * g2v.x + b2v.x;
    float xn1 = (x2.y - mu) * inv * g2v.y + b2v.y;

    float cf = COEF[tok];
    float2 vh2 = *(const float2*)(SS + tok * 384 + 5 * 64 + n);
    float xo0 = xn0 + cf * vh2.x;
    float xo1 = xn1 + cf * vh2.y;

    float2 gg2 = h2f2(GG + (size_t)m * Cc + c);
    *(__half2*)(XO + (size_t)m * Cc + c) = __floats2half2_rn(xo0 * gg2.x, xo1 * gg2.y);
}

// ---------------- host launcher ----------------
static inline int cdiv_(int a, int b) { return (a + b - 1) / b; }

extern "C" void kernel_launch(void* const* d_in, const int* in_sizes, int n_in,
                              void* d_out, int out_size) {
    (void)in_sizes; (void)n_in; (void)out_size;
    const float* x       = (const float*)d_in[0];
    const float* v_first = (const float*)d_in[1];
    const float* x_r  = (const float*)d_in[2];
    const float* x_w  = (const float*)d_in[3];
    const float* x_k  = (const float*)d_in[4];
    const float* x_v  = (const float*)d_in[5];
    const float* x_a  = (const float*)d_in[6];
    const float* x_g  = (const float*)d_in[7];
    const float* w0   = (const float*)d_in[8];
    const float* w1   = (const float*)d_in[9];
    const float* a0   = (const float*)d_in[11];
    const float* a1   = (const float*)d_in[12];
    const float* v0   = (const float*)d_in[14];
    const float* v1   = (const float*)d_in[15];
    const float* g1   = (const float*)d_in[17];
    const float* k_k  = (const float*)d_in[19];
    const float* k_a  = (const float*)d_in[20];
    const float* r_k  = (const float*)d_in[21];
    const float* ln_g = (const float*)d_in[26];
    const float* ln_b = (const float*)d_in[27];

    static cudaStream_t sA = nullptr, sB = nullptr;
    static cudaEvent_t e0 = nullptr, eA = nullptr, eB = nullptr, eA2 = nullptr, eB2 = nullptr;
    if (!sA) {
        cudaStreamCreateWithFlags(&sA, cudaStreamNonBlocking);
        cudaStreamCreateWithFlags(&sB, cudaStreamNonBlocking);
        cudaEventCreateWithFlags(&e0,  cudaEventDisableTiming);
        cudaEventCreateWithFlags(&eA,  cudaEventDisableTiming);
        cudaEventCreateWithFlags(&eB,  cudaEventDisableTiming);
        cudaEventCreateWithFlags(&eA2, cudaEventDisableTiming);
        cudaEventCreateWithFlags(&eB2, cudaEventDisableTiming);
        cudaFuncSetAttribute(k2_gemm_rkv,  cudaFuncAttributeMaxDynamicSharedMemorySize, UP_SMEM);
        cudaFuncSetAttribute(k2_gemm_down, cudaFuncAttributeMaxDynamicSharedMemorySize, UP_SMEM);
        cudaFuncSetAttribute(k2_gemm_out,  cudaFuncAttributeMaxDynamicSharedMemorySize, K2_SMEM);
        cudaFuncSetAttribute(k2_gemm_up,   cudaFuncAttributeMaxDynamicSharedMemorySize, UP_SMEM);
    }

    cudaEventRecord(e0, 0);
    cudaStreamWaitEvent(sA, e0, 0);
    cudaStreamWaitEvent(sB, e0, 0);

    {
        dim3 g(cdiv_(Cc * Cc / 4, 256), 12);
        k_convert_all<<<g, 256, 0, sA>>>((const float*)d_in[22], (const float*)d_in[23],
                                         (const float*)d_in[24], (const float*)d_in[25],
                                         w1, a1, v1, g1,
                                         (const float*)d_in[10], (const float*)d_in[13],
                                         (const float*)d_in[16], (const float*)d_in[18]);
    }
    k_mix<<<cdiv_(Mm * (Cc / 4), 256), 256, 0, sB>>>(x, x_r, x_w, x_k, x_v, x_a, x_g);

    cudaEventRecord(eA, sA);
    cudaEventRecord(eB, sB);
    cudaStreamWaitEvent(sA, eB, 0);
    cudaStreamWaitEvent(sB, eA, 0);

    // phase 2 (balanced): sA = R,K GEMMs (~216us) ; sB = up -> down -> V GEMM (~208us)
    {
        dim3 g(cdiv_(Cc, FBN), Mm / FBM, 2);
        k2_gemm_rkv<<<g, 256, UP_SMEM, sA>>>(0);      // z=0,1 -> R, K
    }
    {
        dim3 g(1, Mm / FBM, 4);
        k2_gemm_up<<<g, 256, UP_SMEM, sB>>>();
    }
    {
        dim3 g(cdiv_(Cc, FBN), Mm / FBM, 4);
        k2_gemm_down<<<g, 256, UP_SMEM, sB>>>();
    }
    {
        dim3 g(cdiv_(Cc, FBN), Mm / FBM, 1);
        k2_gemm_rkv<<<g, 256, UP_SMEM, sB>>>(2);      // z=2 -> V
    }

    cudaEventRecord(eA2, sA);
    cudaEventRecord(eB2, sB);
    cudaStreamWaitEvent(0, eA2, 0);
    cudaStreamWaitEvent(0, eB2, 0);

    k_prepare<<<Mm * Hh / 8, 256>>>(v_first, w0, a0, v0, k_k, k_a, r_k);

    k_scan<<<Bb * Hh * 16, 32>>>();

    k_gn<<<Mm * Hh / 8, 256>>>(ln_g, ln_b);

    {
        dim3 g(cdiv_(Cc, FBN), Mm / FBM);
        k2_gemm_out<<<g, 256, K2_SMEM>>>((float*)d_out);
    }
}

// round 17
// speedup vs baseline: 1.0112x; 1.0112x over previous
#include <cuda_runtime.h>
#include <cuda_fp16.h>
#include <mma.h>
#include <cstdint>

using namespace nvcuda;

// ---------------- problem constants ----------------
namespace {
constexpr int Bb = 4, Tt = 1024, Cc = 960, Hh = 15, Nn = 64;
constexpr int Mm = Bb * Tt;                    // 4096 tokens
constexpr float LN_EPS_F = 0.00064f;
constexpr float EXP_NEG_HALF = 0.6065306597126334f;

constexpr size_t MC  = (size_t)Mm * Cc;
constexpr size_t SZ_H_MC = MC * 2;
constexpr size_t SZ_F_MC = MC * 4;

constexpr size_t O_XR   = 0;
constexpr size_t O_XW   = O_XR + SZ_H_MC;
constexpr size_t O_XK   = O_XW + SZ_H_MC;
constexpr size_t O_XV   = O_XK + SZ_H_MC;
constexpr size_t O_XA   = O_XV + SZ_H_MC;
constexpr size_t O_XG   = O_XA + SZ_H_MC;
constexpr size_t O_WR16 = O_XG + SZ_H_MC;
constexpr size_t O_WK16 = O_WR16 + (size_t)Cc * Cc * 2;
constexpr size_t O_WV16 = O_WK16 + (size_t)Cc * Cc * 2;
constexpr size_t O_WO16 = O_WV16 + (size_t)Cc * Cc * 2;
constexpr size_t O_W116 = O_WO16 + (size_t)Cc * Cc * 2;
constexpr size_t O_A116 = O_W116 + (size_t)Cc * 64 * 2;
constexpr size_t O_V116 = O_A116 + (size_t)Cc * 64 * 2;
constexpr size_t O_G116 = O_V116 + (size_t)Cc * 32 * 2;
constexpr size_t O_W216 = O_G116 + (size_t)Cc * 128 * 2;
constexpr size_t O_A216 = O_W216 + (size_t)64 * Cc * 2;
constexpr size_t O_V216 = O_A216 + (size_t)64 * Cc * 2;
constexpr size_t O_G216 = O_V216 + (size_t)32 * Cc * 2;
constexpr size_t O_HW   = O_G216 + (size_t)128 * Cc * 2;
constexpr size_t O_HA   = O_HW + (size_t)Mm * 64 * 2;
constexpr size_t O_HV   = O_HA + (size_t)Mm * 64 * 2;
constexpr size_t O_HG   = O_HV + (size_t)Mm * 32 * 2;
// fp16 intermediates (fp32-sized slots)
constexpr size_t O_R    = O_HG + (size_t)Mm * 128 * 2;
constexpr size_t O_K    = O_R + SZ_F_MC;
constexpr size_t O_V    = O_K + SZ_F_MC;
constexpr size_t O_WRAW = O_V + SZ_F_MC;
constexpr size_t O_ARAW = O_WRAW + SZ_F_MC;
constexpr size_t O_VRAW = O_ARAW + SZ_F_MC;
constexpr size_t O_GG   = O_VRAW + SZ_F_MC;
// interleaved scan input: [bh][t][6][64] fp32
constexpr size_t O_SS   = O_GG + SZ_F_MC;
constexpr size_t SZ_SS  = (size_t)Bb * Hh * Tt * 6 * 64 * 4;
constexpr size_t O_COEF = O_SS + SZ_SS;
constexpr size_t O_WKV  = O_COEF + (size_t)Bb * Hh * Tt * 4;
constexpr size_t O_XO   = O_WKV + SZ_F_MC;
constexpr size_t SCRATCH_TOTAL = O_XO + SZ_H_MC;

// GEMM config: 128x128 CTA, 8 warps 2Mx4N, 64x32 warp tile (proven)
constexpr int FBM = 128, FBN = 128, FBK = 32;
constexpr int FLDA = 40, FLDB = 136;
constexpr int NSTG = 3;
constexpr int STAGE_A = FBM * FLDA;
constexpr int STAGE_B = FBK * FLDB;
constexpr int K2_SMEM = NSTG * (STAGE_A + STAGE_B) * 2;
constexpr int UPLDC = 132;
constexpr int UP_SMEM = (FBM * UPLDC * 4) > K2_SMEM ? (FBM * UPLDC * 4) : K2_SMEM;

// scan pipeline
constexpr int SCAN_D = 8;
constexpr int SCAN_STAGE_F = 336;
} // namespace

__device__ __align__(256) unsigned char g_scratch[SCRATCH_TOTAL];

// ---------------- helpers ----------------
__device__ __forceinline__ float sigmoidf_(float x) { return 1.f / (1.f + expf(-x)); }
__device__ __forceinline__ float getc(const float4& v, int j) {
    return j == 0 ? v.x : j == 1 ? v.y : j == 2 ? v.z : v.w;
}
__device__ __forceinline__ float2 h2f2(const __half* p) {
    return __half22float2(*(const __half2*)p);
}
__device__ __forceinline__ void cp_async16(void* smem_dst, const void* gsrc) {
    unsigned int d = (unsigned int)__cvta_generic_to_shared(smem_dst);
    asm volatile("cp.async.cg.shared.global [%0], [%1], 16;" :: "r"(d), "l"(gsrc));
}
__device__ __forceinline__ void cp_async16p(void* smem_dst, const void* gsrc, bool pred) {
    unsigned int d = (unsigned int)__cvta_generic_to_shared(smem_dst);
    int b = pred ? 16 : 0;
    asm volatile("cp.async.cg.shared.global [%0], [%1], 16, %2;" :: "r"(d), "l"(gsrc), "r"(b));
}
#define CP_COMMIT() asm volatile("cp.async.commit_group;")
#define CP_WAIT2()  asm volatile("cp.async.wait_group 2;")
#define CP_WAIT7()  asm volatile("cp.async.wait_group 7;")

// ---------------- fused weight convert ----------------
__global__ void k_convert_all(const float* p0, const float* p1, const float* p2,
                              const float* p3, const float* p4, const float* p5,
                              const float* p6, const float* p7, const float* p8,
                              const float* p9, const float* p10, const float* p11) {
    const int sizes[12] = {Cc * Cc, Cc * Cc, Cc * Cc, Cc * Cc,
                           Cc * 64, Cc * 64, Cc * 32, Cc * 128,
                           64 * Cc, 64 * Cc, 32 * Cc, 128 * Cc};
    const size_t doff[12] = {O_WR16, O_WK16, O_WV16, O_WO16,
                             O_W116, O_A116, O_V116, O_G116,
                             O_W216, O_A216, O_V216, O_G216};
    const float* srcs[12] = {p0, p1, p2, p3, p4, p5, p6, p7, p8, p9, p10, p11};
    int z = blockIdx.y;
    int n = sizes[z];
    int i = (blockIdx.x * 256 + threadIdx.x) * 4;
    if (i >= n) return;
    const float* s = srcs[z];
    __half* d = (__half*)(g_scratch + doff[z]);
    float4 v = *(const float4*)(s + i);
    *(__half2*)(d + i)     = __floats2half2_rn(v.x, v.y);
    *(__half2*)(d + i + 2) = __floats2half2_rn(v.z, v.w);
}

// ---------------- token shift + mix ----------------
__global__ void k_mix(const float* __restrict__ x,
                      const float* __restrict__ mr, const float* __restrict__ mw,
                      const float* __restrict__ mk, const float* __restrict__ mv,
                      const float* __restrict__ ma, const float* __restrict__ mg) {
    int i = blockIdx.x * blockDim.x + threadIdx.x;
    if (i >= Mm * (Cc / 4)) return;
    int m = i / (Cc / 4);
    int c = (i % (Cc / 4)) * 4;
    int t = m & (Tt - 1);
    float4 xc = *(const float4*)(x + (size_t)m * Cc + c);
    float4 xp = make_float4(0.f, 0.f, 0.f, 0.f);
    if (t > 0) xp = *(const float4*)(x + (size_t)(m - 1) * Cc + c);
    float4 dx = make_float4(xp.x - xc.x, xp.y - xc.y, xp.z - xc.z, xp.w - xc.w);

    const float* mixes[6] = {mr, mw, mk, mv, ma, mg};
    const size_t offs[6] = {O_XR, O_XW, O_XK, O_XV, O_XA, O_XG};
#pragma unroll
    for (int q = 0; q < 6; q++) {
        float4 mmv = *(const float4*)(mixes[q] + c);
        __half* out = (__half*)(g_scratch + offs[q]);
        __half2 h0 = __floats2half2_rn(xc.x + dx.x * mmv.x, xc.y + dx.y * mmv.y);
        __half2 h1 = __floats2half2_rn(xc.z + dx.z * mmv.z, xc.w + dx.w * mmv.w);
        *(__half2*)(out + (size_t)m * Cc + c)     = h0;
        *(__half2*)(out + (size_t)m * Cc + c + 2) = h1;
    }
}

// ---------------- GEMM compute core: 3-stage cp.async (proven) ----------
__device__ __forceinline__ void gemm_core(const __half* __restrict__ A,
                                          const __half* __restrict__ Bm,
                                          int Nd, int Kd, int bm, int bn,
                                          __half* sA, __half* sB,
                                          wmma::fragment<wmma::accumulator, 16, 16, 16, float> (&acc)[4][2]) {
    int tid = threadIdx.x;
    int warp = tid >> 5;
    int wr = warp >> 2;
    int wc = warp & 3;
    int KT = Kd / FBK;

    auto load_stage = [&](int kt, int s) {
        const __half* Ag = A + (size_t)bm * Kd + kt * FBK;
        __half* sAs = sA + s * STAGE_A;
        __half* sBs = sB + s * STAGE_B;
#pragma unroll
        for (int u = 0; u < 2; u++) {
            int id = tid + u * 256;
            int r = id >> 2;
            int c = (id & 3) * 8;
            cp_async16(sAs + r * FLDA + c, Ag + (size_t)r * Kd + c);
        }
#pragma unroll
        for (int u = 0; u < 2; u++) {
            int id = tid + u * 256;
            int r = id >> 4;
            int c = (id & 15) * 8;
            bool p = (bn + c) < Nd;
            const __half* Bg = Bm + (size_t)(kt * FBK + r) * Nd + bn + c;
            cp_async16p(sBs + r * FLDB + c, p ? Bg : (const __half*)Bm, p);
        }
    };

#pragma unroll
    for (int i = 0; i < 4; i++)
#pragma unroll
        for (int j = 0; j < 2; j++) wmma::fill_fragment(acc[i][j], 0.f);

    load_stage(0, 0);
    CP_COMMIT();
    if (KT > 1) load_stage(1, 1);
    CP_COMMIT();

    for (int kt = 0; kt < KT; kt++) {
        if (kt + 2 < KT) load_stage(kt + 2, (kt + 2) % NSTG);
        CP_COMMIT();
        CP_WAIT2();
        __syncthreads();
        const __half* sAs = sA + (kt % NSTG) * STAGE_A;
        const __half* sBs = sB + (kt % NSTG) * STAGE_B;
#pragma unroll
        for (int ks = 0; ks < 2; ks++) {
            wmma::fragment<wmma::matrix_b, 16, 16, 16, __half, wmma::row_major> fb[2];
            wmma::load_matrix_sync(fb[0], sBs + (ks * 16) * FLDB + wc * 32, FLDB);
            wmma::load_matrix_sync(fb[1], sBs + (ks * 16) * FLDB + wc * 32 + 16, FLDB);
#pragma unroll
            for (int i = 0; i < 4; i++) {
                wmma::fragment<wmma::matrix_a, 16, 16, 16, __half, wmma::row_major> fa;
                wmma::load_matrix_sync(fa, sAs + (wr * 64 + i * 16) * FLDA + ks * 16, FLDA);
                wmma::mma_sync(acc[i][0], fa, fb[0], acc[i][0]);
                wmma::mma_sync(acc[i][1], fa, fb[1], acc[i][1]);
            }
        }
        __syncthreads();
    }
}

// fp32 direct-store GEMM (final output only)
__global__ void __launch_bounds__(256, 2) k2_gemm_out(float* __restrict__ out) {
    extern __shared__ __align__(16) unsigned char dyn[];
    __half* sA = (__half*)dyn;
    __half* sB = sA + NSTG * STAGE_A;
    wmma::fragment<wmma::accumulator, 16, 16, 16, float> acc[4][2];
    int bm = blockIdx.y * FBM;
    int bn = blockIdx.x * FBN;
    gemm_core((const __half*)(g_scratch + O_XO), (const __half*)(g_scratch + O_WO16),
              Cc, Cc, bm, bn, sA, sB, acc);
    int warp = threadIdx.x >> 5;
    int wr = warp >> 2;
    int wc = warp & 3;
#pragma unroll
    for (int i = 0; i < 4; i++)
#pragma unroll
        for (int j = 0; j < 2; j++) {
            int gc = bn + wc * 32 + j * 16;
            if (gc < Cc)
                wmma::store_matrix_sync(out + (size_t)(bm + wr * 64 + i * 16) * Cc + gc,
                                        acc[i][j], Cc, wmma::mem_row_major);
        }
}

// fp16-output GEMM via smem-staged epilogue
__device__ __forceinline__ void gemm_f16_epi(const __half* A, const __half* Bm,
                                             __half* Cout, int Nd, int Kd,
                                             int bm, int bn, unsigned char* dyn) {
    __half* sA = (__half*)dyn;
    __half* sB = sA + NSTG * STAGE_A;
    float*  sC = (float*)dyn;

    wmma::fragment<wmma::accumulator, 16, 16, 16, float> acc[4][2];
    gemm_core(A, Bm, Nd, Kd, bm, bn, sA, sB, acc);

    int tid = threadIdx.x;
    int warp = tid >> 5;
    int wr = warp >> 2;
    int wc = warp & 3;
#pragma unroll
    for (int i = 0; i < 4; i++)
#pragma unroll
        for (int j = 0; j < 2; j++)
            wmma::store_matrix_sync(sC + (wr * 64 + i * 16) * UPLDC + wc * 32 + j * 16,
                                    acc[i][j], UPLDC, wmma::mem_row_major);
    __syncthreads();

    for (int idx = tid; idx < FBM * FBN / 2; idx += 256) {
        int r = idx / (FBN / 2);
        int c2 = (idx % (FBN / 2)) * 2;
        int gc = bn + c2;
        if (gc >= Nd) continue;
        float v0 = sC[r * UPLDC + c2];
        float v1 = sC[r * UPLDC + c2 + 1];
        *(__half2*)(Cout + (size_t)(bm + r) * Nd + gc) = __floats2half2_rn(v0, v1);
    }
}

__global__ void __launch_bounds__(256, 2) k2_gemm_rkv() {
    extern __shared__ __align__(16) unsigned char dyn[];
    int z = blockIdx.z;
    const size_t aoff[3] = {O_XR, O_XK, O_XV};
    const size_t boff[3] = {O_WR16, O_WK16, O_WV16};
    const size_t coff[3] = {O_R, O_K, O_V};
    gemm_f16_epi((const __half*)(g_scratch + aoff[z]), (const __half*)(g_scratch + boff[z]),
                 (__half*)(g_scratch + coff[z]), Cc, Cc,
                 blockIdx.y * FBM, blockIdx.x * FBN, dyn);
}

// down with z offset: z=0..2 (WRAW/ARAW/VRAW) in phase 2, z=3 (GG) deferred
__global__ void __launch_bounds__(256, 2) k2_gemm_down(int z_off) {
    extern __shared__ __align__(16) unsigned char dyn[];
    int z = blockIdx.z + z_off;
    const size_t aoff[4] = {O_HW, O_HA, O_HV, O_HG};
    const size_t boff[4] = {O_W216, O_A216, O_V216, O_G216};
    const size_t coff[4] = {O_WRAW, O_ARAW, O_VRAW, O_GG};
    const int kd[4] = {64, 64, 32, 128};
    gemm_f16_epi((const __half*)(g_scratch + aoff[z]), (const __half*)(g_scratch + boff[z]),
                 (__half*)(g_scratch + coff[z]), Cc, kd[z],
                 blockIdx.y * FBM, blockIdx.x * FBN, dyn);
}

// lora-up: fp16 + activation epilogue via smem staging
__global__ void __launch_bounds__(256, 2) k2_gemm_up() {
    extern __shared__ __align__(16) unsigned char dyn[];
    __half* sA = (__half*)dyn;
    __half* sB = sA + NSTG * STAGE_A;
    float*  sC = (float*)dyn;

    int z = blockIdx.z;
    const size_t aoff[4] = {O_XW, O_XA, O_XV, O_XG};
    const size_t boff[4] = {O_W116, O_A116, O_V116, O_G116};
    const size_t coff[4] = {O_HW, O_HA, O_HV, O_HG};
    const int ndA[4] = {64, 64, 32, 128};
    const int epA[4] = {1, 3, 3, 2};
    int Nd = ndA[z];
    int epi = epA[z];
    int bm = blockIdx.y * FBM;

    wmma::fragment<wmma::accumulator, 16, 16, 16, float> acc[4][2];
    gemm_core((const __half*)(g_scratch + aoff[z]), (const __half*)(g_scratch + boff[z]),
              Nd, Cc, bm, 0, sA, sB, acc);

    int tid = threadIdx.x;
    int warp = tid >> 5;
    int wr = warp >> 2;
    int wc = warp & 3;
#pragma unroll
    for (int i = 0; i < 4; i++)
#pragma unroll
        for (int j = 0; j < 2; j++)
            wmma::store_matrix_sync(sC + (wr * 64 + i * 16) * UPLDC + wc * 32 + j * 16,
                                    acc[i][j], UPLDC, wmma::mem_row_major);
    __syncthreads();

    __half* Cout = (__half*)(g_scratch + coff[z]);
    for (int idx = tid; idx < FBM * 128; idx += 256) {
        int r = idx >> 7;
        int c = idx & 127;
        if (c >= Nd) continue;
        float v = sC[r * UPLDC + c];
        if (epi == 1)      v = tanhf(v);
        else if (epi == 2) v = sigmoidf_(v);
        Cout[(size_t)(bm + r) * Nd + c] = __float2half(v);
    }
}

// ---------------- per-token prepare (fp16 inputs; interleaved [6][64] fp32 out) -----------
__global__ void k_prepare(const float* __restrict__ vfirst,
                          const float* __restrict__ w0, const float* __restrict__ a0,
                          const float* __restrict__ v0, const float* __restrict__ kkw,
                          const float* __restrict__ kaw, const float* __restrict__ rkw) {
    const __half* Rf   = (const __half*)(g_scratch + O_R);
    const __half* Kf   = (const __half*)(g_scratch + O_K);
    const __half* Vf   = (const __half*)(g_scratch + O_V);
    const __half* WRAW = (const __half*)(g_scratch + O_WRAW);
    const __half* ARAW = (const __half*)(g_scratch + O_ARAW);
    const __half* VRAW = (const __half*)(g_scratch + O_VRAW);
    float* SS   = (float*)(g_scratch + O_SS);
    float* COEF = (float*)(g_scratch + O_COEF);

    int gw = (blockIdx.x * blockDim.x + threadIdx.x) >> 5;
    int lane = threadIdx.x & 31;
    if (gw >= Mm * Hh) return;
    int m = gw / Hh;
    int h = gw % Hh;
    int b = m >> 10;
    int t = m & (Tt - 1);
    int n = lane * 2;
    int c = h * Nn + n;
    size_t gbase = (size_t)m * Cc + c;

    float2 k2   = h2f2(Kf + gbase);
    float2 kkwv = *(const float2*)(kkw + c);
    float kkx = k2.x * kkwv.x, kky = k2.y * kkwv.y;
    float ss = kkx * kkx + kky * kky;
#pragma unroll
    for (int o = 16; o; o >>= 1) ss += __shfl_xor_sync(0xffffffffu, ss, o);
    float inv = 1.f / fmaxf(sqrtf(ss), 1e-12f);

    float2 ar2 = h2f2(ARAW + gbase);
    float2 a0v = *(const float2*)(a0 + c);
    float ax = sigmoidf_(a0v.x + ar2.x);
    float ay = sigmoidf_(a0v.y + ar2.y);

    float2 kav = *(const float2*)(kaw + c);
    float khx = k2.x * (1.f + (ax - 1.f) * kav.x);
    float khy = k2.y * (1.f + (ay - 1.f) * kav.y);

    float2 wr2 = h2f2(WRAW + gbase);
    float2 w0v = *(const float2*)(w0 + c);
    float wx = EXP_NEG_HALF * sigmoidf_(w0v.x + wr2.x);
    float wy = EXP_NEG_HALF * sigmoidf_(w0v.y + wr2.y);

    float2 vr2 = h2f2(VRAW + gbase);
    float2 v0v = *(const float2*)(v0 + c);
    float svx = sigmoidf_(v0v.x + vr2.x);
    float svy = sigmoidf_(v0v.y + vr2.y);
    float2 vv  = h2f2(Vf + gbase);
    float2 vf2 = *(const float2*)(vfirst + gbase);
    float vhx = vv.x + (vf2.x - vv.x) * svx;
    float vhy = vv.y + (vf2.y - vv.y) * svy;

    float2 r2  = h2f2(Rf + gbase);
    float2 rkv = *(const float2*)(rkw + c);
    float cf = r2.x * khx * rkv.x + r2.y * khy * rkv.y;
#pragma unroll
    for (int o = 16; o; o >>= 1) cf += __shfl_xor_sync(0xffffffffu, cf, o);

    int bh = b * Hh + h;
    float* tok = SS + ((size_t)bh * Tt + t) * 384 + n;
    *(float2*)(tok + 0 * 64) = make_float2(wx, wy);
    *(float2*)(tok + 1 * 64) = make_float2(-kkx * inv, -kky * inv);
    *(float2*)(tok + 2 * 64) = make_float2(kkx * inv * ax, kky * inv * ay);
    *(float2*)(tok + 3 * 64) = make_float2(khx, khy);
    *(float2*)(tok + 4 * 64) = r2;
    *(float2*)(tok + 5 * 64) = make_float2(vhx, vhy);
    if (lane == 0) COEF[(size_t)bh * Tt + t] = cf;
}

// ---------------- scan: single-warp blocks, no __syncthreads (proven) ------------
__global__ void __launch_bounds__(32) k_scan() {
    __shared__ __align__(16) float sbuf[SCAN_D][SCAN_STAGE_F];

    const float* SS = (const float*)(g_scratch + O_SS);
    float* WKV = (float*)(g_scratch + O_WKV);

    int blk = blockIdx.x;
    int bh = blk >> 4;
    int q = blk & 15;
    int lane = threadIdx.x;
    int rowl = lane >> 3;
    int cg = lane & 7;
    int row = q * 4 + rowl;
    size_t base = (size_t)bh * Tt * Nn;
    size_t base_ss = (size_t)bh * Tt * 384;
    int co = cg * 8;

    auto issue_stage = [&](int t) {
        int slot = t & (SCAN_D - 1);
        const float* src = SS + base_ss + (size_t)t * 384;
#pragma unroll
        for (int c = lane; c < 80; c += 32)
            cp_async16(&sbuf[slot][c * 4], src + c * 4);
        if (lane == 0)
            cp_async16(&sbuf[slot][320], src + 5 * 64 + q * 4);
    };

#pragma unroll
    for (int s = 0; s < SCAN_D - 1; s++) {
        issue_stage(s);
        CP_COMMIT();
    }

    float st[8];
#pragma unroll
    for (int j = 0; j < 8; j++) st[j] = 0.f;

    for (int t = 0; t < Tt; t++) {
        __syncwarp();
        int tp = t + SCAN_D - 1;
        if (tp < Tt) issue_stage(tp);
        CP_COMMIT();
        CP_WAIT7();
        __syncwarp();

        const float* S = sbuf[t & (SCAN_D - 1)];
        float4 wv0 = *(const float4*)(S + 0 * 64 + co);
        float4 wv1 = *(const float4*)(S + 0 * 64 + co + 4);
        float4 av0 = *(const float4*)(S + 1 * 64 + co);
        float4 av1 = *(const float4*)(S + 1 * 64 + co + 4);
        float4 bv0 = *(const float4*)(S + 2 * 64 + co);
        float4 bv1 = *(const float4*)(S + 2 * 64 + co + 4);
        float4 kv0 = *(const float4*)(S + 3 * 64 + co);
        float4 kv1 = *(const float4*)(S + 3 * 64 + co + 4);
        float4 rv0 = *(const float4*)(S + 4 * 64 + co);
        float4 rv1 = *(const float4*)(S + 4 * 64 + co + 4);
        float cv = S[320 + rowl];

        float sa = 0.f;
#pragma unroll
        for (int j = 0; j < 8; j++)
            sa = fmaf(st[j], getc(j < 4 ? av0 : av1, j & 3), sa);
        sa += __shfl_xor_sync(0xffffffffu, sa, 1);
        sa += __shfl_xor_sync(0xffffffffu, sa, 2);
        sa += __shfl_xor_sync(0xffffffffu, sa, 4);

        float outp = 0.f;
#pragma unroll
        for (int j = 0; j < 8; j++) {
            float wj = getc(j < 4 ? wv0 : wv1, j & 3);
            float bj = getc(j < 4 ? bv0 : bv1, j & 3);
            float kj = getc(j < 4 ? kv0 : kv1, j & 3);
            float rj = getc(j < 4 ? rv0 : rv1, j & 3);
            float s = fmaf(st[j], wj, fmaf(sa, bj, cv * kj));
            st[j] = s;
            outp = fmaf(s, rj, outp);
        }
        outp += __shfl_xor_sync(0xffffffffu, outp, 1);
        outp += __shfl_xor_sync(0xffffffffu, outp, 2);
        outp += __shfl_xor_sync(0xffffffffu, outp, 4);
        if (cg == 0) WKV[base + (size_t)t * Nn + row] = outp;
    }
}

// ---------------- groupnorm + bonus + gate ----------------
__global__ void k_gn(const float* __restrict__ lng, const float* __restrict__ lnb) {
    const float* WKV  = (const float*)(g_scratch + O_WKV);
    const float* SS   = (const float*)(g_scratch + O_SS);
    const float* COEF = (const float*)(g_scratch + O_COEF);
    const __half* GG  = (const __half*)(g_scratch + O_GG);
    __half* XO = (__half*)(g_scratch + O_XO);

    int gw = (blockIdx.x * blockDim.x + threadIdx.x) >> 5;
    int lane = threadIdx.x & 31;
    if (gw >= Mm * Hh) return;
    int m = gw / Hh;
    int h = gw % Hh;
    int b = m >> 10;
    int t = m & (Tt - 1);
    int bh = b * Hh + h;
    int n = lane * 2;
    int c = h * Nn + n;
    size_t tok = (size_t)bh * Tt + t;
    size_t sbase = tok * Nn + n;

    float2 x2 = *(const float2*)(WKV + sbase);
    float s1 = x2.x + x2.y;
    float s2 = x2.x * x2.x + x2.y * x2.y;
#pragma unroll
    for (int o = 16; o; o >>= 1) {
        s1 += __shfl_xor_sync(0xffffffffu, s1, o);
        s2 += __shfl_xor_sync(0xffffffffu, s2, o);
    }
    float mu = s1 * (1.f / 64.f);
    float var = s2 * (1.f / 64.f) - mu * mu;
    float inv = rsqrtf(fmaxf(var, 0.f) + LN_EPS_F);

    float2 g2v = *(const float2*)(lng + c);
    float2 b2v = *(const float2*)(lnb + c);
    float xn0 = (x2.x - mu) * inv * g2v.x + b2v.x;
    float xn1 = (x2.y - mu) * inv * g2v.y + b2v.y;

    float cf = COEF[tok];
    float2 vh2 = *(const float2*)(SS + tok * 384 + 5 * 64 + n);
    float xo0 = xn0 + cf * vh2.x;
    float xo1 = xn1 + cf * vh2.y;

    float2 gg2 = h2f2(GG + (size_t)m * Cc + c);
    *(__half2*)(XO + (size_t)m * Cc + c) = __floats2half2_rn(xo0 * gg2.x, xo1 * gg2.y);
}

// ---------------- host launcher ----------------
static inline int cdiv_(int a, int b) { return (a + b - 1) / b; }

extern "C" void kernel_launch(void* const* d_in, const int* in_sizes, int n_in,
                              void* d_out, int out_size) {
    (void)in_sizes; (void)n_in; (void)out_size;
    const float* x       = (const float*)d_in[0];
    const float* v_first = (const float*)d_in[1];
    const float* x_r  = (const float*)d_in[2];
    const float* x_w  = (const float*)d_in[3];
    const float* x_k  = (const float*)d_in[4];
    const float* x_v  = (const float*)d_in[5];
    const float* x_a  = (const float*)d_in[6];
    const float* x_g  = (const float*)d_in[7];
    const float* w0   = (const float*)d_in[8];
    const float* w1   = (const float*)d_in[9];
    const float* a0   = (const float*)d_in[11];
    const float* a1   = (const float*)d_in[12];
    const float* v0   = (const float*)d_in[14];
    const float* v1   = (const float*)d_in[15];
    const float* g1   = (const float*)d_in[17];
    const float* k_k  = (const float*)d_in[19];
    const float* k_a  = (const float*)d_in[20];
    const float* r_k  = (const float*)d_in[21];
    const float* ln_g = (const float*)d_in[26];
    const float* ln_b = (const float*)d_in[27];

    static cudaStream_t sA = nullptr, sB = nullptr;
    static cudaEvent_t e0 = nullptr, eA = nullptr, eB = nullptr, eA2 = nullptr, eB2 = nullptr, eG = nullptr;
    if (!sA) {
        cudaStreamCreateWithFlags(&sA, cudaStreamNonBlocking);
        cudaStreamCreateWithFlags(&sB, cudaStreamNonBlocking);
        cudaEventCreateWithFlags(&e0,  cudaEventDisableTiming);
        cudaEventCreateWithFlags(&eA,  cudaEventDisableTiming);
        cudaEventCreateWithFlags(&eB,  cudaEventDisableTiming);
        cudaEventCreateWithFlags(&eA2, cudaEventDisableTiming);
        cudaEventCreateWithFlags(&eB2, cudaEventDisableTiming);
        cudaEventCreateWithFlags(&eG,  cudaEventDisableTiming);
        cudaFuncSetAttribute(k2_gemm_rkv,  cudaFuncAttributeMaxDynamicSharedMemorySize, UP_SMEM);
        cudaFuncSetAttribute(k2_gemm_down, cudaFuncAttributeMaxDynamicSharedMemorySize, UP_SMEM);
        cudaFuncSetAttribute(k2_gemm_out,  cudaFuncAttributeMaxDynamicSharedMemorySize, K2_SMEM);
        cudaFuncSetAttribute(k2_gemm_up,   cudaFuncAttributeMaxDynamicSharedMemorySize, UP_SMEM);
    }

    cudaEventRecord(e0, 0);
    cudaStreamWaitEvent(sA, e0, 0);
    cudaStreamWaitEvent(sB, e0, 0);

    {
        dim3 g(cdiv_(Cc * Cc / 4, 256), 12);
        k_convert_all<<<g, 256, 0, sA>>>((const float*)d_in[22], (const float*)d_in[23],
                                         (const float*)d_in[24], (const float*)d_in[25],
                                         w1, a1, v1, g1,
                                         (const float*)d_in[10], (const float*)d_in[13],
                                         (const float*)d_in[16], (const float*)d_in[18]);
    }
    k_mix<<<cdiv_(Mm * (Cc / 4), 256), 256, 0, sB>>>(x, x_r, x_w, x_k, x_v, x_a, x_g);

    cudaEventRecord(eA, sA);
    cudaEventRecord(eB, sB);
    cudaStreamWaitEvent(sA, eB, 0);
    cudaStreamWaitEvent(sB, eA, 0);

    // phase 2 (R13 layout): sA = rkv x3 ; sB = up(all) -> down z=0..2
    {
        dim3 g(cdiv_(Cc, FBN), Mm / FBM, 3);
        k2_gemm_rkv<<<g, 256, UP_SMEM, sA>>>();
    }
    {
        dim3 g(1, Mm / FBM, 4);
        k2_gemm_up<<<g, 256, UP_SMEM, sB>>>();
    }
    {
        dim3 g(cdiv_(Cc, FBN), Mm / FBM, 3);
        k2_gemm_down<<<g, 256, UP_SMEM, sB>>>(0);     // WRAW, ARAW, VRAW
    }

    cudaEventRecord(eA2, sA);
    cudaEventRecord(eB2, sB);
    cudaStreamWaitEvent(0, eA2, 0);
    cudaStreamWaitEvent(0, eB2, 0);

    // critical path: prepare -> scan (GG not needed yet)
    k_prepare<<<Mm * Hh / 8, 256>>>(v_first, w0, a0, v0, k_k, k_a, r_k);
    k_scan<<<Bb * Hh * 16, 32>>>();

    // deferred GG down-GEMM (z=3) hides under prepare+scan on sB
    {
        dim3 g(cdiv_(Cc, FBN), Mm / FBM, 1);
        k2_gemm_down<<<g, 256, UP_SMEM, sB>>>(3);     // GG
    }
    cudaEventRecord(eG, sB);
    cudaStreamWaitEvent(0, eG, 0);

    k_gn<<<Mm * Hh / 8, 256>>>(ln_g, ln_b);

    {
        dim3 g(cdiv_(Cc, FBN), Mm / FBM);
        k2_gemm_out<<<g, 256, K2_SMEM>>>((float*)d_out);
    }
}